// round 1
// baseline (speedup 1.0000x reference)
#include <cuda_runtime.h>
#include <math.h>

#define MAXN   25600
#define D_IN   1068
#define FDIM   768
#define G4     3072
#define NPE    200
#define MAXDOC 256

// ---------------- scratch (static device arrays; no allocations) ----------------
__device__ float SC_PE  [NPE * D_IN];
__device__ int   SC_POS [MAXN];
__device__ float SC_XDOC[(size_t)MAXN * D_IN];
__device__ float SC_WT  [15 * 256 * D_IN];            // taps 0..2 (k3), 3..7 (k5), 8..14 (k7)
__device__ float SC_FEAT[(size_t)MAXN * FDIM];
__device__ float SC_POOL[(size_t)MAXN * FDIM];
__device__ float SC_G   [(size_t)MAXN * G4];
__device__ float SC_HS  [(size_t)MAXN * FDIM];
__device__ float SC_CS  [(size_t)MAXN * FDIM];
__device__ float SC_H16 [2][16 * FDIM];               // double-buffered scan h state
__device__ unsigned SC_ARRIVE;
__device__ unsigned SC_RELEASE;

__device__ __forceinline__ float sigm(float x) { return 1.0f / (1.0f + expf(-x)); }

// ---------------- pos index ----------------
__global__ void k_posidx(const int* __restrict__ dl, int ndocs, int N) {
    __shared__ int off[MAXDOC + 1];
    if (threadIdx.x == 0) {
        int s = 0;
        for (int d = 0; d < ndocs; ++d) { off[d] = s; s += dl[d]; }
        off[ndocs] = s;
    }
    __syncthreads();
    for (int n = threadIdx.x; n < N; n += blockDim.x) {
        int lo = 0, hi = ndocs;
        while (hi - lo > 1) { int mid = (lo + hi) >> 1; if (off[mid] <= n) lo = mid; else hi = mid; }
        SC_POS[n] = n - off[lo];
    }
}

// ---------------- positional-encoding table ----------------
__global__ void k_pe() {
    int idx = blockIdx.x * blockDim.x + threadIdx.x;
    if (idx >= NPE * D_IN) return;
    int pos = idx / D_IN, ch = idx % D_IN;
    int i = ch >> 1;
    float e = (2.0f * (float)i) / (float)D_IN;
    float p = powf(10000.0f, e);
    float ang = (float)pos / p;
    SC_PE[idx] = (ch & 1) ? cosf(ang) : sinf(ang);
}

__global__ void k_addpe(const float* __restrict__ x, int N) {
    long long idx = (long long)blockIdx.x * blockDim.x + threadIdx.x;
    long long tot = (long long)N * D_IN;
    if (idx >= tot) return;
    int n  = (int)(idx / D_IN);
    int ch = (int)(idx % D_IN);
    SC_XDOC[idx] = x[idx] + SC_PE[SC_POS[n] * D_IN + ch];
}

// ---------------- conv weight re-layout: [oc][c][t] -> [t][oc][c] ----------------
__global__ void k_wtrans(const float* __restrict__ w, int ksz, int dstOff) {
    int idx = blockIdx.x * blockDim.x + threadIdx.x;
    int tot = ksz * 256 * D_IN;
    if (idx >= tot) return;
    int t  = idx / (256 * D_IN);
    int r  = idx - t * 256 * D_IN;
    int oc = r / D_IN;
    int c  = r - oc * D_IN;
    SC_WT[dstOff + (t * 256 + oc) * D_IN + c] = w[((size_t)oc * D_IN + c) * ksz + t];
}

// ---------------- conv as tap-accumulated GEMM (64x64x16, fp32) ----------------
__global__ void k_conv(const float* __restrict__ bias, int N, int ksz, int wtOff, int ocBase) {
    __shared__ float As[16][68];
    __shared__ float Bs[16][68];
    int tid = threadIdx.x;
    int m0 = blockIdx.x * 64, n0 = blockIdx.y * 64;
    int tx = tid & 15, ty = tid >> 4;
    int loadRow = tid >> 2;
    int loadK = (tid & 3) * 4;
    float acc[4][4] = {};
    int pad = ksz >> 1;
    const float* wbase = SC_WT + wtOff;

    for (int t = 0; t < ksz; ++t) {
        int aRow = m0 + loadRow + t - pad;
        bool av = (aRow >= 0 && aRow < N);
        const float* ap = SC_XDOC + (long long)aRow * D_IN;
        const float* bp = wbase + ((long long)t * 256 + n0 + loadRow) * D_IN;
        for (int k0 = 0; k0 < D_IN; k0 += 16) {
            int kc = k0 + loadK;
            bool kv = (kc < D_IN);   // 1068 % 4 == 0 -> float4 never straddles the edge
            float4 a = (av && kv) ? *(const float4*)(ap + kc) : make_float4(0.f, 0.f, 0.f, 0.f);
            float4 b = kv ? *(const float4*)(bp + kc) : make_float4(0.f, 0.f, 0.f, 0.f);
            As[loadK + 0][loadRow] = a.x; As[loadK + 1][loadRow] = a.y;
            As[loadK + 2][loadRow] = a.z; As[loadK + 3][loadRow] = a.w;
            Bs[loadK + 0][loadRow] = b.x; Bs[loadK + 1][loadRow] = b.y;
            Bs[loadK + 2][loadRow] = b.z; Bs[loadK + 3][loadRow] = b.w;
            __syncthreads();
#pragma unroll
            for (int kk = 0; kk < 16; ++kk) {
                float4 a4 = *(const float4*)&As[kk][ty * 4];
                float4 b4 = *(const float4*)&Bs[kk][tx * 4];
                acc[0][0] = fmaf(a4.x, b4.x, acc[0][0]); acc[0][1] = fmaf(a4.x, b4.y, acc[0][1]);
                acc[0][2] = fmaf(a4.x, b4.z, acc[0][2]); acc[0][3] = fmaf(a4.x, b4.w, acc[0][3]);
                acc[1][0] = fmaf(a4.y, b4.x, acc[1][0]); acc[1][1] = fmaf(a4.y, b4.y, acc[1][1]);
                acc[1][2] = fmaf(a4.y, b4.z, acc[1][2]); acc[1][3] = fmaf(a4.y, b4.w, acc[1][3]);
                acc[2][0] = fmaf(a4.z, b4.x, acc[2][0]); acc[2][1] = fmaf(a4.z, b4.y, acc[2][1]);
                acc[2][2] = fmaf(a4.z, b4.z, acc[2][2]); acc[2][3] = fmaf(a4.z, b4.w, acc[2][3]);
                acc[3][0] = fmaf(a4.w, b4.x, acc[3][0]); acc[3][1] = fmaf(a4.w, b4.y, acc[3][1]);
                acc[3][2] = fmaf(a4.w, b4.z, acc[3][2]); acc[3][3] = fmaf(a4.w, b4.w, acc[3][3]);
            }
            __syncthreads();
        }
    }
#pragma unroll
    for (int i = 0; i < 4; ++i) {
        int m = m0 + ty * 4 + i;
        if (m < N) {
#pragma unroll
            for (int j = 0; j < 4; ++j) {
                int oc = n0 + tx * 4 + j;
                float v = acc[i][j] + bias[oc];
                v = (v >= 0.f) ? v : 0.01f * v;             // LeakyReLU
                SC_FEAT[(long long)m * FDIM + ocBase + oc] = v;
            }
        }
    }
}

// ---------------- max pool (same padding, post-ReLU) ----------------
__global__ void k_pool(int N) {
    long long idx = (long long)blockIdx.x * blockDim.x + threadIdx.x;
    long long tot = (long long)N * FDIM;
    if (idx >= tot) return;
    int n = (int)(idx / FDIM), ch = (int)(idx % FDIM);
    int ksz = 3 + 2 * (ch >> 8);
    int p = ksz >> 1;
    float m = -1e30f;
    for (int d = -p; d <= p; ++d) {
        int nn = n + d;
        if (nn >= 0 && nn < N) m = fmaxf(m, SC_FEAT[(long long)nn * FDIM + ch]);
    }
    SC_POOL[idx] = m;
}

// ---------------- generic SGEMM-NT into SC_G: C[M,3072] (+)= A[M,768] @ B[3072,768]^T ----------------
// aSel: 0=SC_POOL, 1=SC_FEAT, 2=SC_HS ; A row r reads row (r+shift), zero if outside [0,N)
__global__ void k_sgemm(int aSel, const float* __restrict__ B, int N, int shift,
                        const float* __restrict__ b1, const float* __restrict__ b2, int accum) {
    __shared__ float As[16][68];
    __shared__ float Bs[16][68];
    const float* A = (aSel == 0) ? SC_POOL : ((aSel == 1) ? SC_FEAT : SC_HS);
    int tid = threadIdx.x;
    int m0 = blockIdx.x * 64, n0 = blockIdx.y * 64;
    int tx = tid & 15, ty = tid >> 4;
    int loadRow = tid >> 2;
    int loadK = (tid & 3) * 4;
    float acc[4][4] = {};

    int aRow = m0 + loadRow + shift;
    bool av = (aRow >= 0 && aRow < N);
    const float* ap = A + (long long)aRow * FDIM;
    const float* bp = B + (long long)(n0 + loadRow) * FDIM;

    for (int k0 = 0; k0 < FDIM; k0 += 16) {
        float4 a = av ? *(const float4*)(ap + k0 + loadK) : make_float4(0.f, 0.f, 0.f, 0.f);
        float4 b = *(const float4*)(bp + k0 + loadK);
        As[loadK + 0][loadRow] = a.x; As[loadK + 1][loadRow] = a.y;
        As[loadK + 2][loadRow] = a.z; As[loadK + 3][loadRow] = a.w;
        Bs[loadK + 0][loadRow] = b.x; Bs[loadK + 1][loadRow] = b.y;
        Bs[loadK + 2][loadRow] = b.z; Bs[loadK + 3][loadRow] = b.w;
        __syncthreads();
#pragma unroll
        for (int kk = 0; kk < 16; ++kk) {
            float4 a4 = *(const float4*)&As[kk][ty * 4];
            float4 b4 = *(const float4*)&Bs[kk][tx * 4];
            acc[0][0] = fmaf(a4.x, b4.x, acc[0][0]); acc[0][1] = fmaf(a4.x, b4.y, acc[0][1]);
            acc[0][2] = fmaf(a4.x, b4.z, acc[0][2]); acc[0][3] = fmaf(a4.x, b4.w, acc[0][3]);
            acc[1][0] = fmaf(a4.y, b4.x, acc[1][0]); acc[1][1] = fmaf(a4.y, b4.y, acc[1][1]);
            acc[1][2] = fmaf(a4.y, b4.z, acc[1][2]); acc[1][3] = fmaf(a4.y, b4.w, acc[1][3]);
            acc[2][0] = fmaf(a4.z, b4.x, acc[2][0]); acc[2][1] = fmaf(a4.z, b4.y, acc[2][1]);
            acc[2][2] = fmaf(a4.z, b4.z, acc[2][2]); acc[2][3] = fmaf(a4.z, b4.w, acc[2][3]);
            acc[3][0] = fmaf(a4.w, b4.x, acc[3][0]); acc[3][1] = fmaf(a4.w, b4.y, acc[3][1]);
            acc[3][2] = fmaf(a4.w, b4.z, acc[3][2]); acc[3][3] = fmaf(a4.w, b4.w, acc[3][3]);
        }
        __syncthreads();
    }
#pragma unroll
    for (int i = 0; i < 4; ++i) {
        int m = m0 + ty * 4 + i;
        if (m < N) {
#pragma unroll
            for (int j = 0; j < 4; ++j) {
                int g = n0 + tx * 4 + j;
                long long o = (long long)m * G4 + g;
                if (accum) {
                    SC_G[o] += acc[i][j];
                } else {
                    float bv = (b1 ? b1[g] : 0.f) + (b2 ? b2[g] : 0.f);
                    SC_G[o] = acc[i][j] + bv;
                }
            }
        }
    }
}

// ---------------- barrier/state reset ----------------
__global__ void k_reset() {
    int idx = blockIdx.x * blockDim.x + threadIdx.x;
    if (idx == 0) { SC_ARRIVE = 0u; SC_RELEASE = 0u; }
    if (idx < 16 * FDIM) SC_H16[0][idx] = 0.f;
}

// ---------------- persistent chunked-LSTM scan ----------------
// 128 blocks x 384 threads (all co-resident). Block b owns h_idx range [b*6, b*6+6) x 4 gates x 16 lanes j.
// thread: j = t&15, q = t>>4 in [0,24): hl = q%6, gate = q/6.
__global__ void k_scan(const float* __restrict__ Whh, int N, int nChunks) {
    __shared__ float4 sh4[16 * 192];                 // exactly 48 KB, XOR-swizzled h tile
    float* shp = (float*)sh4;
    int t = threadIdx.x, b = blockIdx.x;
    int j = t & 15;
    int q = t >> 4;
    int hl = q % 6, gate = q / 6;
    int h_idx = b * 6 + hl;
    int grow = gate * FDIM + h_idx;
    const float4* w4 = (const float4*)(Whh + (long long)grow * FDIM);
    float c_reg = 0.f;

    for (int s = 0; s < nChunks; ++s) {
        // load previous-step h (double buffer; L1 bypass for cross-SM coherence)
        const float4* src = (const float4*)(SC_H16[s & 1]);
        for (int f = t; f < 3072; f += 384) {
            float4 v = __ldcg(src + f);
            int jj = f / 192, k4 = f - jj * 192;
            sh4[jj * 192 + (k4 ^ jj)] = v;
        }
        __syncthreads();

        int pos = s * 16 + j;
        float pre = 0.f;
        if (pos < N) {
            const float4* h4 = sh4 + j * 192;
            float a0 = 0.f, a1 = 0.f, a2 = 0.f, a3 = 0.f;
#pragma unroll 4
            for (int k4 = 0; k4 < 192; ++k4) {
                float4 w = __ldg(w4 + k4);
                float4 h = h4[k4 ^ j];
                a0 = fmaf(w.x, h.x, a0); a1 = fmaf(w.y, h.y, a1);
                a2 = fmaf(w.z, h.z, a2); a3 = fmaf(w.w, h.w, a3);
            }
            pre = __ldg(&SC_G[(long long)pos * G4 + grow]) + ((a0 + a1) + (a2 + a3));
        }
        __syncthreads();
        shp[j * 24 + q] = pre;                        // reuse shared (all reads of sh4 done)
        __syncthreads();

        if (q < 6 && pos < N) {
            float gi = shp[j * 24 + hl];
            float gf = shp[j * 24 + 6  + hl];
            float gg = shp[j * 24 + 12 + hl];
            float go = shp[j * 24 + 18 + hl];
            float c2 = sigm(gf) * c_reg + sigm(gi) * tanhf(gg);
            float h2 = sigm(go) * tanhf(c2);
            c_reg = c2;
            long long o = (long long)pos * FDIM + h_idx;
            SC_HS[o] = h2;
            SC_CS[o] = c2;
            SC_H16[(s + 1) & 1][j * FDIM + h_idx] = h2;
        }

        // software grid barrier (all 128 blocks co-resident on 148 SMs)
        __threadfence();
        __syncthreads();
        if (t == 0) {
            unsigned prev = atomicAdd(&SC_ARRIVE, 1u);
            unsigned target = (unsigned)(s + 1) * gridDim.x;
            if (prev + 1 == target) {
                atomicExch(&SC_RELEASE, (unsigned)(s + 1));
            } else {
                while (*(volatile unsigned*)&SC_RELEASE < (unsigned)(s + 1)) __nanosleep(64);
            }
            __threadfence();
        }
        __syncthreads();
    }
}

// ---------------- final LSTM-cell gate fuse ----------------
__global__ void k_final(float* __restrict__ out, int N, int shift, int outOff) {
    long long idx = (long long)blockIdx.x * blockDim.x + threadIdx.x;
    long long tot = (long long)N * FDIM;
    if (idx >= tot) return;
    int n = (int)(idx / FDIM), h = (int)(idx % FDIM);
    int ns = n + shift;
    float cin = (ns >= 0 && ns < N) ? SC_CS[(long long)ns * FDIM + h] : 0.f;
    const float* g = SC_G + (long long)n * G4;
    float gi = g[h], gf = g[FDIM + h], gg = g[2 * FDIM + h], go = g[3 * FDIM + h];
    float c2 = sigm(gf) * cin + sigm(gi) * tanhf(gg);
    out[(long long)n * 1536 + outOff + h] = sigm(go) * tanhf(c2);
}

// ---------------- launch ----------------
extern "C" void kernel_launch(void* const* d_in, const int* in_sizes, int n_in,
                              void* d_out, int out_size) {
    const float* x    = (const float*)d_in[0];
    const int*   dl   = (const int*)  d_in[1];
    const float* cw0  = (const float*)d_in[2];  const float* cb0 = (const float*)d_in[3];
    const float* cw1  = (const float*)d_in[4];  const float* cb1 = (const float*)d_in[5];
    const float* cw2  = (const float*)d_in[6];  const float* cb2 = (const float*)d_in[7];
    const float* Wih  = (const float*)d_in[8];  const float* Whh  = (const float*)d_in[9];
    const float* bih  = (const float*)d_in[10]; const float* bhh  = (const float*)d_in[11];
    const float* WihR = (const float*)d_in[12]; const float* WhhR = (const float*)d_in[13];
    const float* bihR = (const float*)d_in[14]; const float* bhhR = (const float*)d_in[15];
    float* out = (float*)d_out;

    int ndocs = in_sizes[1];
    int N = out_size / 1536;
    if (N > MAXN) N = MAXN;
    int nChunks = (N + 15) / 16;

    k_posidx<<<1, 256>>>(dl, ndocs, N);
    k_pe<<<(NPE * D_IN + 255) / 256, 256>>>();
    {
        long long tot = (long long)N * D_IN;
        k_addpe<<<(int)((tot + 255) / 256), 256>>>(x, N);
    }
    k_wtrans<<<(3 * 256 * D_IN + 255) / 256, 256>>>(cw0, 3, 0);
    k_wtrans<<<(5 * 256 * D_IN + 255) / 256, 256>>>(cw1, 5, 3 * 256 * D_IN);
    k_wtrans<<<(7 * 256 * D_IN + 255) / 256, 256>>>(cw2, 7, 8 * 256 * D_IN);

    dim3 cg((N + 63) / 64, 4);
    k_conv<<<cg, 256>>>(cb0, N, 3, 0,              0);
    k_conv<<<cg, 256>>>(cb1, N, 5, 3 * 256 * D_IN, 256);
    k_conv<<<cg, 256>>>(cb2, N, 7, 8 * 256 * D_IN, 512);

    {
        long long tot = (long long)N * FDIM;
        k_pool<<<(int)((tot + 255) / 256), 256>>>(N);
    }

    dim3 gg((N + 63) / 64, G4 / 64);
    // gate pre-activations for the scan: gx = pool @ Wih^T + b_ih + b_hh
    k_sgemm<<<gg, 256>>>(0, Wih, N, 0, bih, bhh, 0);
    k_reset<<<48, 256>>>();
    k_scan<<<128, 384>>>(Whh, N, nChunks);

    // forward final cell: G = feat @ Wih^T + b ; G += h_prev @ Whh^T ; gates -> out[:, :768]
    k_sgemm<<<gg, 256>>>(1, Wih, N, 0, bih, bhh, 0);
    k_sgemm<<<gg, 256>>>(2, Whh, N, -9, (const float*)0, (const float*)0, 1);
    {
        long long tot = (long long)N * FDIM;
        k_final<<<(int)((tot + 255) / 256), 256>>>(out, N, -9, 0);
    }
    // reverse final cell: out[:, 768:]
    k_sgemm<<<gg, 256>>>(1, WihR, N, 0, bihR, bhhR, 0);
    k_sgemm<<<gg, 256>>>(2, WhhR, N, 9, (const float*)0, (const float*)0, 1);
    {
        long long tot = (long long)N * FDIM;
        k_final<<<(int)((tot + 255) / 256), 256>>>(out, N, 9, 768);
    }
}

// round 2
// speedup vs baseline: 1.7319x; 1.7319x over previous
#include <cuda_runtime.h>
#include <math.h>

#define MAXN   25600
#define D_IN   1068
#define FDIM   768
#define G4     3072
#define NPE    200
#define MAXDOC 256

typedef unsigned long long ull;

// ---------------- scratch (static device arrays; no allocations) ----------------
__device__ float SC_PE  [NPE * D_IN];
__device__ int   SC_POS [MAXN];
__device__ float SC_XDOC[(size_t)MAXN * D_IN];
__device__ float SC_WT  [15 * 256 * D_IN];            // taps 0..2 (k3), 3..7 (k5), 8..14 (k7)
__device__ float SC_FEAT[(size_t)MAXN * FDIM];
__device__ float SC_POOL[(size_t)MAXN * FDIM];
__device__ float SC_G   [(size_t)MAXN * G4];
__device__ float SC_HS  [(size_t)MAXN * FDIM];
__device__ float SC_CS  [(size_t)MAXN * FDIM];
__device__ float SC_H16 [2][16 * FDIM];               // double-buffered scan h state
__device__ unsigned SC_ARRIVE;
__device__ unsigned SC_RELEASE;

__device__ __forceinline__ float sigm(float x) { return 1.0f / (1.0f + expf(-x)); }

// ---- packed f32x2 helpers (sm_103a; ptxas never auto-fuses, must be PTX) ----
__device__ __forceinline__ ull pk2(float x) {
    ull r; asm("mov.b64 %0, {%1, %1};" : "=l"(r) : "f"(x)); return r;
}
__device__ __forceinline__ void ffma2(ull& d, ull a, ull b) {
    asm("fma.rn.f32x2 %0, %1, %2, %0;" : "+l"(d) : "l"(a), "l"(b));
}
__device__ __forceinline__ float2 up2(ull v) {
    float2 r; asm("mov.b64 {%0, %1}, %2;" : "=f"(r.x), "=f"(r.y) : "l"(v)); return r;
}

#define SWZ(f) ((f) ^ (((f) >> 3) & 7))     // float4-index swizzle within a 32-f4 row

// ---------------- pos index ----------------
__global__ void k_posidx(const int* __restrict__ dl, int ndocs, int N) {
    __shared__ int off[MAXDOC + 1];
    if (threadIdx.x == 0) {
        int s = 0;
        for (int d = 0; d < ndocs; ++d) { off[d] = s; s += dl[d]; }
        off[ndocs] = s;
    }
    __syncthreads();
    for (int n = threadIdx.x; n < N; n += blockDim.x) {
        int lo = 0, hi = ndocs;
        while (hi - lo > 1) { int mid = (lo + hi) >> 1; if (off[mid] <= n) lo = mid; else hi = mid; }
        SC_POS[n] = n - off[lo];
    }
}

// ---------------- positional-encoding table ----------------
__global__ void k_pe() {
    int idx = blockIdx.x * blockDim.x + threadIdx.x;
    if (idx >= NPE * D_IN) return;
    int pos = idx / D_IN, ch = idx % D_IN;
    int i = ch >> 1;
    float e = (2.0f * (float)i) / (float)D_IN;
    float p = powf(10000.0f, e);
    float ang = (float)pos / p;
    SC_PE[idx] = (ch & 1) ? cosf(ang) : sinf(ang);
}

__global__ void k_addpe(const float* __restrict__ x, int N) {
    long long idx = (long long)blockIdx.x * blockDim.x + threadIdx.x;
    long long tot = (long long)N * D_IN;
    if (idx >= tot) return;
    int n  = (int)(idx / D_IN);
    int ch = (int)(idx % D_IN);
    SC_XDOC[idx] = x[idx] + SC_PE[SC_POS[n] * D_IN + ch];
}

// ---------------- conv weight re-layout: [oc][c][t] -> [t][oc][c] ----------------
__global__ void k_wtrans(const float* __restrict__ w, int ksz, int dstOff) {
    int idx = blockIdx.x * blockDim.x + threadIdx.x;
    int tot = ksz * 256 * D_IN;
    if (idx >= tot) return;
    int t  = idx / (256 * D_IN);
    int r  = idx - t * 256 * D_IN;
    int oc = r / D_IN;
    int c  = r - oc * D_IN;
    SC_WT[dstOff + (t * 256 + oc) * D_IN + c] = w[((size_t)oc * D_IN + c) * ksz + t];
}

// ================= 128x128x32 f32x2 GEMM core (shared by conv & gate kernels) ==========
// smem layout: S[k][m] k-major, row stride 132 floats, float4 index swizzled by SWZ.
// loader: 256 threads x 4 iters; idx=tid+i*256; row=idx>>3 (0..127), kg=idx&7 (f4 within 32k).
#define GEMM_LOAD(Sm, ptr, lda, rowBase, rowLim, KD, k0)                               \
    _Pragma("unroll")                                                                  \
    for (int i_ = 0; i_ < 4; ++i_) {                                                   \
        int idx_ = tid + i_ * 256;                                                     \
        int row_ = idx_ >> 3, kg_ = idx_ & 7;                                          \
        int kc_ = (k0) + kg_ * 4;                                                      \
        int ar_ = (rowBase) + row_;                                                    \
        float4 v_ = make_float4(0.f, 0.f, 0.f, 0.f);                                   \
        if (ar_ >= 0 && ar_ < (rowLim) && kc_ < (KD))                                  \
            v_ = *(const float4*)((ptr) + (size_t)ar_ * (lda) + kc_);                  \
        float* d_ = Sm + SWZ(row_ >> 2) * 4 + (row_ & 3);                              \
        d_[(kg_ * 4 + 0) * 132] = v_.x; d_[(kg_ * 4 + 1) * 132] = v_.y;                \
        d_[(kg_ * 4 + 2) * 132] = v_.z; d_[(kg_ * 4 + 3) * 132] = v_.w;                \
    }

#define GEMM_ROW(i_, val_)                                                             \
    { ull aa_ = pk2(val_);                                                             \
      ffma2(acc[i_][0], aa_, bq0.x); ffma2(acc[i_][1], aa_, bq0.y);                    \
      ffma2(acc[i_][2], aa_, bq1.x); ffma2(acc[i_][3], aa_, bq1.y); }

#define GEMM_COMPUTE()                                                                 \
    _Pragma("unroll 8")                                                                \
    for (int kk = 0; kk < 32; ++kk) {                                                  \
        const float* ar_ = As + kk * 132;                                              \
        const float* br_ = Bs + kk * 132;                                              \
        float4 a0 = *(const float4*)(ar_ + 4 * SWZ(ty * 2));                           \
        float4 a1 = *(const float4*)(ar_ + 4 * SWZ(ty * 2 + 1));                       \
        ulonglong2 bq0 = *(const ulonglong2*)(br_ + 4 * SWZ(tx * 2));                  \
        ulonglong2 bq1 = *(const ulonglong2*)(br_ + 4 * SWZ(tx * 2 + 1));              \
        GEMM_ROW(0, a0.x) GEMM_ROW(1, a0.y) GEMM_ROW(2, a0.z) GEMM_ROW(3, a0.w)        \
        GEMM_ROW(4, a1.x) GEMM_ROW(5, a1.y) GEMM_ROW(6, a1.z) GEMM_ROW(7, a1.w)        \
    }

// ---------------- conv as tap-accumulated GEMM ----------------
__global__ __launch_bounds__(256, 2)
void k_gconv(const float* __restrict__ bias, int N, int ksz, int wtOff, int ocBase) {
    __shared__ float As[32 * 132];
    __shared__ float Bs[32 * 132];
    int tid = threadIdx.x;
    int m0 = blockIdx.x * 128, n0 = blockIdx.y * 128;
    int tx = tid & 15, ty = tid >> 4;
    ull acc[8][4] = {};
    int pad = ksz >> 1;

    for (int t = 0; t < ksz; ++t) {
        const float* Bp = SC_WT + wtOff + (size_t)t * 256 * D_IN;
        int sh = t - pad;
        for (int k0 = 0; k0 < D_IN; k0 += 32) {
            GEMM_LOAD(As, SC_XDOC, D_IN, m0 + sh, N, D_IN, k0)
            GEMM_LOAD(Bs, Bp, D_IN, n0, 256, D_IN, k0)
            __syncthreads();
            GEMM_COMPUTE()
            __syncthreads();
        }
    }
#pragma unroll
    for (int i = 0; i < 8; ++i) {
        int m = m0 + ty * 8 + i;
        if (m < N) {
#pragma unroll
            for (int jp = 0; jp < 4; ++jp) {
                float2 v = up2(acc[i][jp]);
                int oc = n0 + tx * 8 + jp * 2;
                float v0 = v.x + bias[oc], v1 = v.y + bias[oc + 1];
                v0 = (v0 >= 0.f) ? v0 : 0.01f * v0;
                v1 = (v1 >= 0.f) ? v1 : 0.01f * v1;
                SC_FEAT[(long long)m * FDIM + ocBase + oc]     = v0;
                SC_FEAT[(long long)m * FDIM + ocBase + oc + 1] = v1;
            }
        }
    }
}

// ---------------- gate GEMM: SC_G = A1@B1^T [+ A2(shift)@B2^T] + b1 + b2 ----------------
// a1Sel: 0 = SC_POOL, 1 = SC_FEAT. A2 (if useA2) = SC_HS with row shift, zero outside [0,N)
__global__ __launch_bounds__(256, 2)
void k_ggate(int a1Sel, const float* __restrict__ B1, int useA2, const float* __restrict__ B2,
             int shift, const float* __restrict__ b1, const float* __restrict__ b2, int N) {
    __shared__ float As[32 * 132];
    __shared__ float Bs[32 * 132];
    int tid = threadIdx.x;
    int m0 = blockIdx.x * 128, n0 = blockIdx.y * 128;
    int tx = tid & 15, ty = tid >> 4;
    ull acc[8][4] = {};

    int nPass = useA2 ? 2 : 1;
    for (int p = 0; p < nPass; ++p) {
        const float* A = (p == 0) ? (a1Sel ? SC_FEAT : SC_POOL) : SC_HS;
        const float* B = (p == 0) ? B1 : B2;
        int sh = (p == 0) ? 0 : shift;
        for (int k0 = 0; k0 < FDIM; k0 += 32) {
            GEMM_LOAD(As, A, FDIM, m0 + sh, N, FDIM, k0)
            GEMM_LOAD(Bs, B, FDIM, n0, G4, FDIM, k0)
            __syncthreads();
            GEMM_COMPUTE()
            __syncthreads();
        }
    }
#pragma unroll
    for (int i = 0; i < 8; ++i) {
        int m = m0 + ty * 8 + i;
        if (m < N) {
#pragma unroll
            for (int jp = 0; jp < 4; ++jp) {
                float2 v = up2(acc[i][jp]);
                int g = n0 + tx * 8 + jp * 2;
                float bv0 = b1[g]     + (b2 ? b2[g]     : 0.f);
                float bv1 = b1[g + 1] + (b2 ? b2[g + 1] : 0.f);
                SC_G[(long long)m * G4 + g]     = v.x + bv0;
                SC_G[(long long)m * G4 + g + 1] = v.y + bv1;
            }
        }
    }
}

// ---------------- max pool (same padding, post-ReLU) ----------------
__global__ void k_pool(int N) {
    long long idx = (long long)blockIdx.x * blockDim.x + threadIdx.x;
    long long tot = (long long)N * FDIM;
    if (idx >= tot) return;
    int n = (int)(idx / FDIM), ch = (int)(idx % FDIM);
    int ksz = 3 + 2 * (ch >> 8);
    int p = ksz >> 1;
    float m = -1e30f;
    for (int d = -p; d <= p; ++d) {
        int nn = n + d;
        if (nn >= 0 && nn < N) m = fmaxf(m, SC_FEAT[(long long)nn * FDIM + ch]);
    }
    SC_POOL[idx] = m;
}

// ---------------- barrier/state reset ----------------
__global__ void k_reset() {
    int idx = blockIdx.x * blockDim.x + threadIdx.x;
    if (idx == 0) { SC_ARRIVE = 0u; SC_RELEASE = 0u; }
    if (idx < 16 * FDIM) SC_H16[0][idx] = 0.f;
}

// ---------------- persistent chunked-LSTM scan ----------------
// 128 blocks x 384 threads (all co-resident). Block b owns h rows [b*6, b*6+6) x 4 gates x 16 lanes j.
__global__ void k_scan(const float* __restrict__ Whh, int N, int nChunks) {
    __shared__ float4 sh4[16 * 192];                 // 48 KB, XOR-swizzled h tile
    float* shp = (float*)sh4;
    int t = threadIdx.x, b = blockIdx.x;
    int j = t & 15;
    int q = t >> 4;
    int hl = q % 6, gate = q / 6;
    int h_idx = b * 6 + hl;
    int grow = gate * FDIM + h_idx;
    const float4* w4 = (const float4*)(Whh + (long long)grow * FDIM);
    float c_reg = 0.f;

    for (int s = 0; s < nChunks; ++s) {
        const float4* src = (const float4*)(SC_H16[s & 1]);
        for (int f = t; f < 3072; f += 384) {
            float4 v = __ldcg(src + f);
            int jj = f / 192, k4 = f - jj * 192;
            sh4[jj * 192 + (k4 ^ jj)] = v;
        }
        __syncthreads();

        int pos = s * 16 + j;
        float pre = 0.f;
        if (pos < N) {
            const float4* h4 = sh4 + j * 192;
            ull acc0 = 0, acc1 = 0;
#pragma unroll 4
            for (int k4 = 0; k4 < 192; ++k4) {
                float4 w = __ldg(w4 + k4);
                float4 h = h4[k4 ^ j];
                ull wlo, whi, hlo, hhi;
                asm("mov.b64 %0, {%1, %2};" : "=l"(wlo) : "f"(w.x), "f"(w.y));
                asm("mov.b64 %0, {%1, %2};" : "=l"(whi) : "f"(w.z), "f"(w.w));
                asm("mov.b64 %0, {%1, %2};" : "=l"(hlo) : "f"(h.x), "f"(h.y));
                asm("mov.b64 %0, {%1, %2};" : "=l"(hhi) : "f"(h.z), "f"(h.w));
                ffma2(acc0, wlo, hlo);
                ffma2(acc1, whi, hhi);
            }
            float2 s0 = up2(acc0), s1 = up2(acc1);
            pre = __ldg(&SC_G[(long long)pos * G4 + grow]) + ((s0.x + s0.y) + (s1.x + s1.y));
        }
        __syncthreads();
        shp[j * 24 + q] = pre;
        __syncthreads();

        if (q < 6 && pos < N) {
            float gi = shp[j * 24 + hl];
            float gf = shp[j * 24 + 6  + hl];
            float gg = shp[j * 24 + 12 + hl];
            float go = shp[j * 24 + 18 + hl];
            float c2 = sigm(gf) * c_reg + sigm(gi) * tanhf(gg);
            float h2 = sigm(go) * tanhf(c2);
            c_reg = c2;
            long long o = (long long)pos * FDIM + h_idx;
            SC_HS[o] = h2;
            SC_CS[o] = c2;
            SC_H16[(s + 1) & 1][j * FDIM + h_idx] = h2;
        }

        __threadfence();
        __syncthreads();
        if (t == 0) {
            unsigned prev = atomicAdd(&SC_ARRIVE, 1u);
            unsigned target = (unsigned)(s + 1) * gridDim.x;
            if (prev + 1 == target) {
                atomicExch(&SC_RELEASE, (unsigned)(s + 1));
            } else {
                while (*(volatile unsigned*)&SC_RELEASE < (unsigned)(s + 1)) __nanosleep(64);
            }
            __threadfence();
        }
        __syncthreads();
    }
}

// ---------------- final LSTM-cell gate fuse ----------------
__global__ void k_final(float* __restrict__ out, int N, int shift, int outOff) {
    long long idx = (long long)blockIdx.x * blockDim.x + threadIdx.x;
    long long tot = (long long)N * FDIM;
    if (idx >= tot) return;
    int n = (int)(idx / FDIM), h = (int)(idx % FDIM);
    int ns = n + shift;
    float cin = (ns >= 0 && ns < N) ? SC_CS[(long long)ns * FDIM + h] : 0.f;
    const float* g = SC_G + (long long)n * G4;
    float gi = g[h], gf = g[FDIM + h], gg = g[2 * FDIM + h], go = g[3 * FDIM + h];
    float c2 = sigm(gf) * cin + sigm(gi) * tanhf(gg);
    out[(long long)n * 1536 + outOff + h] = sigm(go) * tanhf(c2);
}

// ---------------- launch ----------------
extern "C" void kernel_launch(void* const* d_in, const int* in_sizes, int n_in,
                              void* d_out, int out_size) {
    const float* x    = (const float*)d_in[0];
    const int*   dl   = (const int*)  d_in[1];
    const float* cw0  = (const float*)d_in[2];  const float* cb0 = (const float*)d_in[3];
    const float* cw1  = (const float*)d_in[4];  const float* cb1 = (const float*)d_in[5];
    const float* cw2  = (const float*)d_in[6];  const float* cb2 = (const float*)d_in[7];
    const float* Wih  = (const float*)d_in[8];  const float* Whh  = (const float*)d_in[9];
    const float* bih  = (const float*)d_in[10]; const float* bhh  = (const float*)d_in[11];
    const float* WihR = (const float*)d_in[12]; const float* WhhR = (const float*)d_in[13];
    const float* bihR = (const float*)d_in[14]; const float* bhhR = (const float*)d_in[15];
    float* out = (float*)d_out;

    int ndocs = in_sizes[1];
    int N = out_size / 1536;
    if (N > MAXN) N = MAXN;
    int nChunks = (N + 15) / 16;

    k_posidx<<<1, 256>>>(dl, ndocs, N);
    k_pe<<<(NPE * D_IN + 255) / 256, 256>>>();
    {
        long long tot = (long long)N * D_IN;
        k_addpe<<<(int)((tot + 255) / 256), 256>>>(x, N);
    }
    k_wtrans<<<(3 * 256 * D_IN + 255) / 256, 256>>>(cw0, 3, 0);
    k_wtrans<<<(5 * 256 * D_IN + 255) / 256, 256>>>(cw1, 5, 3 * 256 * D_IN);
    k_wtrans<<<(7 * 256 * D_IN + 255) / 256, 256>>>(cw2, 7, 8 * 256 * D_IN);

    dim3 cg((N + 127) / 128, 2);
    k_gconv<<<cg, 256>>>(cb0, N, 3, 0,              0);
    k_gconv<<<cg, 256>>>(cb1, N, 5, 3 * 256 * D_IN, 256);
    k_gconv<<<cg, 256>>>(cb2, N, 7, 8 * 256 * D_IN, 512);

    {
        long long tot = (long long)N * FDIM;
        k_pool<<<(int)((tot + 255) / 256), 256>>>(N);
    }

    dim3 gg((N + 127) / 128, G4 / 128);
    // gate pre-activations for the scan: gx = pool @ Wih^T + b_ih + b_hh
    k_ggate<<<gg, 256>>>(0, Wih, 0, (const float*)0, 0, bih, bhh, N);
    k_reset<<<48, 256>>>();
    k_scan<<<128, 384>>>(Whh, N, nChunks);

    // forward final cell (fused): G = feat@Wih^T + h(-9)@Whh^T + b ; gates -> out[:, :768]
    k_ggate<<<gg, 256>>>(1, Wih, 1, Whh, -9, bih, bhh, N);
    {
        long long tot = (long long)N * FDIM;
        k_final<<<(int)((tot + 255) / 256), 256>>>(out, N, -9, 0);
    }
    // reverse final cell: out[:, 768:]
    k_ggate<<<gg, 256>>>(1, WihR, 1, WhhR, 9, bihR, bhhR, N);
    {
        long long tot = (long long)N * FDIM;
        k_final<<<(int)((tot + 255) / 256), 256>>>(out, N, 9, 768);
    }
}

// round 4
// speedup vs baseline: 2.1417x; 1.2366x over previous
#include <cuda_runtime.h>
#include <cuda_bf16.h>
#include <math.h>
#include <stdint.h>

#define MAXN   25600
#define D_IN   1068
#define KPADX  1088
#define FDIM   768
#define G4     3072
#define NPE    200
#define MAXDOC 256

typedef unsigned long long ull;

// ---------------- scratch (static device arrays; no allocations) ----------------
__device__ float SC_PE  [NPE * D_IN];
__device__ int   SC_POS [MAXN];
__device__ float SC_XDOC[(size_t)MAXN * D_IN];
__device__ float SC_WT  [15 * 256 * D_IN];            // taps: 0..2 (k3), 3..7 (k5), 8..14 (k7)
__device__ float SC_FEAT[(size_t)MAXN * FDIM];
__device__ float SC_POOL[(size_t)MAXN * FDIM];
__device__ float SC_G   [(size_t)MAXN * G4];
__device__ float SC_HS  [(size_t)MAXN * FDIM];
__device__ float SC_CS  [(size_t)MAXN * FDIM];
__device__ float SC_H16 [2][16 * FDIM];
__device__ unsigned SC_ARRIVE;
__device__ unsigned SC_RELEASE;

// bf16 split planes (hi + lo), 16B aligned for cp.async
__device__ __align__(16) __nv_bfloat16 XBh[(size_t)MAXN * KPADX], XBl[(size_t)MAXN * KPADX];
__device__ __align__(16) __nv_bfloat16 WTBh[(size_t)3840 * KPADX], WTBl[(size_t)3840 * KPADX];
__device__ __align__(16) __nv_bfloat16 FBh[(size_t)MAXN * FDIM], FBl[(size_t)MAXN * FDIM];
__device__ __align__(16) __nv_bfloat16 PBh[(size_t)MAXN * FDIM], PBl[(size_t)MAXN * FDIM];
__device__ __align__(16) __nv_bfloat16 HBh[(size_t)MAXN * FDIM], HBl[(size_t)MAXN * FDIM];
__device__ __align__(16) __nv_bfloat16 WGBh[(size_t)4 * G4 * FDIM], WGBl[(size_t)4 * G4 * FDIM];

__device__ __forceinline__ float sigm(float x) { return 1.0f / (1.0f + expf(-x)); }

// ---- packed f32x2 helpers (scan) ----
__device__ __forceinline__ void ffma2(ull& d, ull a, ull b) {
    asm("fma.rn.f32x2 %0, %1, %2, %0;" : "+l"(d) : "l"(a), "l"(b));
}
__device__ __forceinline__ float2 up2(ull v) {
    float2 r; asm("mov.b64 {%0, %1}, %2;" : "=f"(r.x), "=f"(r.y) : "l"(v)); return r;
}

// ---- mma.sync / ldmatrix / cp.async (base PTX, compute_103-safe) ----
__device__ __forceinline__ uint32_t smem_u32(const void* p) {
    uint32_t a;
    asm("{ .reg .u64 t; cvta.to.shared.u64 t, %1; cvt.u32.u64 %0, t; }" : "=r"(a) : "l"(p));
    return a;
}
__device__ __forceinline__ void ldsm4(uint32_t* r, uint32_t addr) {
    asm volatile("ldmatrix.sync.aligned.m8n8.x4.shared.b16 {%0,%1,%2,%3}, [%4];"
        : "=r"(r[0]), "=r"(r[1]), "=r"(r[2]), "=r"(r[3]) : "r"(addr));
}
__device__ __forceinline__ void mma16816(float* c, const uint32_t* a, uint32_t b0, uint32_t b1) {
    asm volatile("mma.sync.aligned.m16n8k16.row.col.f32.bf16.bf16.f32 "
        "{%0,%1,%2,%3}, {%4,%5,%6,%7}, {%8,%9}, {%0,%1,%2,%3};"
        : "+f"(c[0]), "+f"(c[1]), "+f"(c[2]), "+f"(c[3])
        : "r"(a[0]), "r"(a[1]), "r"(a[2]), "r"(a[3]), "r"(b0), "r"(b1));
}
__device__ __forceinline__ void cpa16(uint32_t dst, const void* src, int valid) {
    asm volatile("cp.async.cg.shared.global [%0], [%1], 16, %2;"
        :: "r"(dst), "l"(src), "r"(valid ? 16 : 0) : "memory");
}
#define CP_COMMIT() asm volatile("cp.async.commit_group;" ::: "memory")
#define CP_WAIT1()  asm volatile("cp.async.wait_group 1;" ::: "memory")
#define CP_WAIT0()  asm volatile("cp.async.wait_group 0;" ::: "memory")

// ---- SMEM: 4 planes (Ah, Al, Bh, Bl) of 128 rows x 32 bf16, row stride 80B; 2 buffers ----
#define RS     80
#define PLANE  10240
#define BUFB   40960
#define SMEM_MMA (2 * BUFB)

// load one 128x32 plane (2 chunks of 16B per thread)
__device__ __forceinline__ void ldp(uint32_t sdst, const __nv_bfloat16* src, int ldk,
                                    int rowBase, int rowLim, int kcol, int tid) {
#pragma unroll
    for (int it = 0; it < 2; ++it) {
        int ch = tid + it * 256;
        int row = ch >> 2, c = ch & 3;
        int r = rowBase + row;
        int v = (r >= 0 && r < rowLim);
        const void* s = src + ((size_t)(v ? r : 0) * ldk + kcol + c * 8);
        cpa16(sdst + row * RS + c * 16, s, v);
    }
}

// per-warp compute on one 32-K block: 3 split combos, acc[2][8][4]
__device__ __forceinline__ void wcompute(uint32_t sbuf, int lane, int wm, int wn,
                                         float acc[2][8][4]) {
    int arow = wm * 32 + (lane & 15);
    int brow = wn * 64 + (lane & 7) + ((lane >> 4) << 3);
#pragma unroll
    for (int kh = 0; kh < 2; ++kh) {
        int acol = kh * 16 + ((lane >> 4) << 3);
        int bcol = kh * 16 + (((lane >> 3) & 1) << 3);
        uint32_t ah[2][4], al[2][4], bh[4][4], bl[4][4];
#pragma unroll
        for (int mt = 0; mt < 2; ++mt) {
            uint32_t ad = sbuf + (arow + mt * 16) * RS + acol * 2;
            ldsm4(ah[mt], ad);
            ldsm4(al[mt], ad + PLANE);
        }
#pragma unroll
        for (int g = 0; g < 4; ++g) {
            uint32_t bd = sbuf + 2 * PLANE + (brow + g * 16) * RS + bcol * 2;
            ldsm4(bh[g], bd);
            ldsm4(bl[g], bd + PLANE);
        }
#pragma unroll
        for (int mt = 0; mt < 2; ++mt)
#pragma unroll
            for (int nt = 0; nt < 8; ++nt) {
                int g = nt >> 1, hb = (nt & 1) * 2;
                mma16816(acc[mt][nt], ah[mt], bh[g][hb], bh[g][hb + 1]);
                mma16816(acc[mt][nt], ah[mt], bl[g][hb], bl[g][hb + 1]);
                mma16816(acc[mt][nt], al[mt], bh[g][hb], bh[g][hb + 1]);
            }
    }
}

// ---------------- small kernels ----------------
__global__ void k_posidx(const int* __restrict__ dl, int ndocs, int N) {
    __shared__ int off[MAXDOC + 1];
    if (threadIdx.x == 0) {
        int s = 0;
        for (int d = 0; d < ndocs; ++d) { off[d] = s; s += dl[d]; }
        off[ndocs] = s;
    }
    __syncthreads();
    for (int n = threadIdx.x; n < N; n += blockDim.x) {
        int lo = 0, hi = ndocs;
        while (hi - lo > 1) { int mid = (lo + hi) >> 1; if (off[mid] <= n) lo = mid; else hi = mid; }
        SC_POS[n] = n - off[lo];
    }
}

__global__ void k_pe() {
    int idx = blockIdx.x * blockDim.x + threadIdx.x;
    if (idx >= NPE * D_IN) return;
    int pos = idx / D_IN, ch = idx % D_IN;
    int i = ch >> 1;
    float e = (2.0f * (float)i) / (float)D_IN;
    float ang = (float)pos / powf(10000.0f, e);
    SC_PE[idx] = (ch & 1) ? cosf(ang) : sinf(ang);
}

__global__ void k_addpe(const float* __restrict__ x, int N) {
    long long idx = (long long)blockIdx.x * blockDim.x + threadIdx.x;
    long long tot = (long long)N * D_IN;
    if (idx >= tot) return;
    int n  = (int)(idx / D_IN);
    int ch = (int)(idx % D_IN);
    SC_XDOC[idx] = x[idx] + SC_PE[SC_POS[n] * D_IN + ch];
}

__global__ void k_wtrans(const float* __restrict__ w, int ksz, int dstOff) {
    int idx = blockIdx.x * blockDim.x + threadIdx.x;
    int tot = ksz * 256 * D_IN;
    if (idx >= tot) return;
    int t  = idx / (256 * D_IN);
    int r  = idx - t * 256 * D_IN;
    int oc = r / D_IN;
    int c  = r - oc * D_IN;
    SC_WT[dstOff + (t * 256 + oc) * D_IN + c] = w[((size_t)oc * D_IN + c) * ksz + t];
}

// fp32 -> bf16 (hi, lo) split; sel chooses src/dst
__global__ void k_cvt(int sel, int rows) {
    const float* src; __nv_bfloat16 *hi, *lo; int K, Kpad, ld;
    switch (sel) {
        case 0: src = SC_XDOC; hi = XBh;  lo = XBl;  K = D_IN; Kpad = KPADX; ld = D_IN; break;
        case 1: src = SC_WT;   hi = WTBh; lo = WTBl; K = D_IN; Kpad = KPADX; ld = D_IN; break;
        case 2: src = SC_FEAT; hi = FBh;  lo = FBl;  K = FDIM; Kpad = FDIM;  ld = FDIM; break;
        case 3: src = SC_POOL; hi = PBh;  lo = PBl;  K = FDIM; Kpad = FDIM;  ld = FDIM; break;
        default:src = SC_HS;   hi = HBh;  lo = HBl;  K = FDIM; Kpad = FDIM;  ld = FDIM; break;
    }
    long long idx = (long long)blockIdx.x * blockDim.x + threadIdx.x;
    long long tot = (long long)rows * Kpad;
    if (idx >= tot) return;
    int r = (int)(idx / Kpad), k = (int)(idx % Kpad);
    float v = (k < K) ? src[(size_t)r * ld + k] : 0.f;
    __nv_bfloat16 h = __float2bfloat16(v);
    hi[idx] = h;
    lo[idx] = __float2bfloat16(v - __bfloat162float(h));
}

__global__ void k_cvtw(const float* __restrict__ src, int slot) {
    int idx = blockIdx.x * blockDim.x + threadIdx.x;
    const int tot = G4 * FDIM;
    if (idx >= tot) return;
    float v = src[idx];
    __nv_bfloat16 h = __float2bfloat16(v);
    size_t o = (size_t)slot * tot + idx;
    WGBh[o] = h;
    WGBl[o] = __float2bfloat16(v - __bfloat162float(h));
}

// ---------------- mma conv: SC_FEAT[:, ocBase+n0 .. +128] ----------------
__global__ __launch_bounds__(256, 1)
void k_mmconv(int ksz, int tapBase, int ocBase, const float* __restrict__ bias, int N) {
    extern __shared__ char smem[];
    uint32_t sb = smem_u32(smem);
    int tid = threadIdx.x, lane = tid & 31, wid = tid >> 5;
    int wm = wid & 3, wn = wid >> 2;
    int m0 = blockIdx.x * 128, n0 = blockIdx.y * 128;
    int pad = ksz >> 1;
    int nblk = ksz * 34;
    float acc[2][8][4] = {};

    auto load_blk = [&](int i) {
        int buf = i & 1;
        int p = i / 34, kb = i - p * 34;
        int sh = p - pad;
        uint32_t bb = sb + buf * BUFB;
        const __nv_bfloat16* wth = WTBh + (size_t)(tapBase + p) * 256 * KPADX;
        const __nv_bfloat16* wtl = WTBl + (size_t)(tapBase + p) * 256 * KPADX;
        ldp(bb,             XBh, KPADX, m0 + sh, N,   kb * 32, tid);
        ldp(bb + PLANE,     XBl, KPADX, m0 + sh, N,   kb * 32, tid);
        ldp(bb + 2 * PLANE, wth, KPADX, n0,      256, kb * 32, tid);
        ldp(bb + 3 * PLANE, wtl, KPADX, n0,      256, kb * 32, tid);
        CP_COMMIT();
    };

    load_blk(0);
    for (int i = 0; i < nblk; ++i) {
        if (i + 1 < nblk) { load_blk(i + 1); CP_WAIT1(); } else { CP_WAIT0(); }
        __syncthreads();
        wcompute(sb + (i & 1) * BUFB, lane, wm, wn, acc);
        __syncthreads();
    }

#pragma unroll
    for (int mt = 0; mt < 2; ++mt)
#pragma unroll
        for (int nt = 0; nt < 8; ++nt) {
            int col = n0 + wn * 64 + nt * 8 + (lane & 3) * 2;
            float b0 = bias[col], b1 = bias[col + 1];
            int r0 = m0 + wm * 32 + mt * 16 + (lane >> 2);
#pragma unroll
            for (int hh = 0; hh < 2; ++hh) {
                int m = r0 + hh * 8;
                if (m < N) {
                    float v0 = acc[mt][nt][hh * 2]     + b0;
                    float v1 = acc[mt][nt][hh * 2 + 1] + b1;
                    v0 = (v0 >= 0.f) ? v0 : 0.01f * v0;
                    v1 = (v1 >= 0.f) ? v1 : 0.01f * v1;
                    SC_FEAT[(size_t)m * FDIM + ocBase + col]     = v0;
                    SC_FEAT[(size_t)m * FDIM + ocBase + col + 1] = v1;
                }
            }
        }
}

// ---------------- mma gate GEMM: SC_G = A@W^T [+ A2(shift)@W2^T] + b1 + b2 ----------------
__global__ __launch_bounds__(256, 1)
void k_mmgate(int aSel, int wSlot, int pass2, int wSlot2, int shift2,
              const float* __restrict__ b1, const float* __restrict__ b2, int N) {
    extern __shared__ char smem[];
    uint32_t sb = smem_u32(smem);
    int tid = threadIdx.x, lane = tid & 31, wid = tid >> 5;
    int wm = wid & 3, wn = wid >> 2;
    int m0 = blockIdx.x * 128, n0 = blockIdx.y * 128;
    int nblk = pass2 ? 48 : 24;
    float acc[2][8][4] = {};

    auto load_blk = [&](int i) {
        int buf = i & 1;
        int p = i / 24, kb = i - p * 24;
        const __nv_bfloat16 *ah, *al, *bh, *bl;
        int sh;
        if (p == 0) {
            ah = aSel ? FBh : PBh; al = aSel ? FBl : PBl;
            bh = WGBh + (size_t)wSlot * G4 * FDIM;
            bl = WGBl + (size_t)wSlot * G4 * FDIM;
            sh = 0;
        } else {
            ah = HBh; al = HBl;
            bh = WGBh + (size_t)wSlot2 * G4 * FDIM;
            bl = WGBl + (size_t)wSlot2 * G4 * FDIM;
            sh = shift2;
        }
        uint32_t bb = sb + buf * BUFB;
        ldp(bb,             ah, FDIM, m0 + sh, N,  kb * 32, tid);
        ldp(bb + PLANE,     al, FDIM, m0 + sh, N,  kb * 32, tid);
        ldp(bb + 2 * PLANE, bh, FDIM, n0,      G4, kb * 32, tid);
        ldp(bb + 3 * PLANE, bl, FDIM, n0,      G4, kb * 32, tid);
        CP_COMMIT();
    };

    load_blk(0);
    for (int i = 0; i < nblk; ++i) {
        if (i + 1 < nblk) { load_blk(i + 1); CP_WAIT1(); } else { CP_WAIT0(); }
        __syncthreads();
        wcompute(sb + (i & 1) * BUFB, lane, wm, wn, acc);
        __syncthreads();
    }

#pragma unroll
    for (int mt = 0; mt < 2; ++mt)
#pragma unroll
        for (int nt = 0; nt < 8; ++nt) {
            int g = n0 + wn * 64 + nt * 8 + (lane & 3) * 2;
            float bv0 = b1[g] + b2[g];
            float bv1 = b1[g + 1] + b2[g + 1];
            int r0 = m0 + wm * 32 + mt * 16 + (lane >> 2);
#pragma unroll
            for (int hh = 0; hh < 2; ++hh) {
                int m = r0 + hh * 8;
                if (m < N) {
                    SC_G[(size_t)m * G4 + g]     = acc[mt][nt][hh * 2]     + bv0;
                    SC_G[(size_t)m * G4 + g + 1] = acc[mt][nt][hh * 2 + 1] + bv1;
                }
            }
        }
}

// ---------------- max pool ----------------
__global__ void k_pool(int N) {
    long long idx = (long long)blockIdx.x * blockDim.x + threadIdx.x;
    long long tot = (long long)N * FDIM;
    if (idx >= tot) return;
    int n = (int)(idx / FDIM), ch = (int)(idx % FDIM);
    int ksz = 3 + 2 * (ch >> 8);
    int p = ksz >> 1;
    float m = -1e30f;
    for (int d = -p; d <= p; ++d) {
        int nn = n + d;
        if (nn >= 0 && nn < N) m = fmaxf(m, SC_FEAT[(long long)nn * FDIM + ch]);
    }
    SC_POOL[idx] = m;
}

__global__ void k_reset() {
    int idx = blockIdx.x * blockDim.x + threadIdx.x;
    if (idx == 0) { SC_ARRIVE = 0u; SC_RELEASE = 0u; }
    if (idx < 16 * FDIM) SC_H16[0][idx] = 0.f;
}

// ---------------- persistent chunked-LSTM scan ----------------
__global__ void k_scan(const float* __restrict__ Whh, int N, int nChunks) {
    __shared__ float4 sh4[16 * 192];
    float* shp = (float*)sh4;
    int t = threadIdx.x, b = blockIdx.x;
    int j = t & 15;
    int q = t >> 4;
    int hl = q % 6, gate = q / 6;
    int h_idx = b * 6 + hl;
    int grow = gate * FDIM + h_idx;
    const float4* w4 = (const float4*)(Whh + (long long)grow * FDIM);
    float c_reg = 0.f;

    for (int s = 0; s < nChunks; ++s) {
        const float4* src = (const float4*)(SC_H16[s & 1]);
        for (int f = t; f < 3072; f += 384) {
            float4 v = __ldcg(src + f);
            int jj = f / 192, k4 = f - jj * 192;
            sh4[jj * 192 + (k4 ^ jj)] = v;
        }
        __syncthreads();

        int pos = s * 16 + j;
        float pre = 0.f;
        if (pos < N) {
            const float4* h4 = sh4 + j * 192;
            ull acc0 = 0, acc1 = 0;
#pragma unroll 4
            for (int k4 = 0; k4 < 192; ++k4) {
                float4 w = __ldg(w4 + k4);
                float4 h = h4[k4 ^ j];
                ull wlo, whi, hlo, hhi;
                asm("mov.b64 %0, {%1, %2};" : "=l"(wlo) : "f"(w.x), "f"(w.y));
                asm("mov.b64 %0, {%1, %2};" : "=l"(whi) : "f"(w.z), "f"(w.w));
                asm("mov.b64 %0, {%1, %2};" : "=l"(hlo) : "f"(h.x), "f"(h.y));
                asm("mov.b64 %0, {%1, %2};" : "=l"(hhi) : "f"(h.z), "f"(h.w));
                ffma2(acc0, wlo, hlo);
                ffma2(acc1, whi, hhi);
            }
            float2 s0 = up2(acc0), s1 = up2(acc1);
            pre = __ldg(&SC_G[(long long)pos * G4 + grow]) + ((s0.x + s0.y) + (s1.x + s1.y));
        }
        __syncthreads();
        shp[j * 24 + q] = pre;
        __syncthreads();

        if (q < 6 && pos < N) {
            float gi = shp[j * 24 + hl];
            float gf = shp[j * 24 + 6  + hl];
            float gg = shp[j * 24 + 12 + hl];
            float go = shp[j * 24 + 18 + hl];
            float c2 = sigm(gf) * c_reg + sigm(gi) * tanhf(gg);
            float h2 = sigm(go) * tanhf(c2);
            c_reg = c2;
            long long o = (long long)pos * FDIM + h_idx;
            SC_HS[o] = h2;
            SC_CS[o] = c2;
            SC_H16[(s + 1) & 1][j * FDIM + h_idx] = h2;
        }

        __threadfence();
        __syncthreads();
        if (t == 0) {
            unsigned prev = atomicAdd(&SC_ARRIVE, 1u);
            unsigned target = (unsigned)(s + 1) * gridDim.x;
            if (prev + 1 == target) {
                atomicExch(&SC_RELEASE, (unsigned)(s + 1));
            } else {
                while (*(volatile unsigned*)&SC_RELEASE < (unsigned)(s + 1)) __nanosleep(64);
            }
            __threadfence();
        }
        __syncthreads();
    }
}

// ---------------- final LSTM-cell gate fuse ----------------
__global__ void k_final(float* __restrict__ out, int N, int shift, int outOff) {
    long long idx = (long long)blockIdx.x * blockDim.x + threadIdx.x;
    long long tot = (long long)N * FDIM;
    if (idx >= tot) return;
    int n = (int)(idx / FDIM), h = (int)(idx % FDIM);
    int ns = n + shift;
    float cin = (ns >= 0 && ns < N) ? SC_CS[(long long)ns * FDIM + h] : 0.f;
    const float* g = SC_G + (long long)n * G4;
    float gi = g[h], gf = g[FDIM + h], gg = g[2 * FDIM + h], go = g[3 * FDIM + h];
    float c2 = sigm(gf) * cin + sigm(gi) * tanhf(gg);
    out[(long long)n * 1536 + outOff + h] = sigm(go) * tanhf(c2);
}

// ---------------- launch ----------------
extern "C" void kernel_launch(void* const* d_in, const int* in_sizes, int n_in,
                              void* d_out, int out_size) {
    const float* x    = (const float*)d_in[0];
    const int*   dl   = (const int*)  d_in[1];
    const float* cw0  = (const float*)d_in[2];  const float* cb0 = (const float*)d_in[3];
    const float* cw1  = (const float*)d_in[4];  const float* cb1 = (const float*)d_in[5];
    const float* cw2  = (const float*)d_in[6];  const float* cb2 = (const float*)d_in[7];
    const float* Wih  = (const float*)d_in[8];  const float* Whh  = (const float*)d_in[9];
    const float* bih  = (const float*)d_in[10]; const float* bhh  = (const float*)d_in[11];
    const float* WihR = (const float*)d_in[12]; const float* WhhR = (const float*)d_in[13];
    const float* bihR = (const float*)d_in[14]; const float* bhhR = (const float*)d_in[15];
    float* out = (float*)d_out;

    int ndocs = in_sizes[1];
    int N = out_size / 1536;
    if (N > MAXN) N = MAXN;
    int nChunks = (N + 15) / 16;

    cudaFuncSetAttribute(k_mmconv, cudaFuncAttributeMaxDynamicSharedMemorySize, SMEM_MMA);
    cudaFuncSetAttribute(k_mmgate, cudaFuncAttributeMaxDynamicSharedMemorySize, SMEM_MMA);

    k_posidx<<<1, 256>>>(dl, ndocs, N);
    k_pe<<<(NPE * D_IN + 255) / 256, 256>>>();
    {
        long long tot = (long long)N * D_IN;
        k_addpe<<<(int)((tot + 255) / 256), 256>>>(x, N);
    }
    k_wtrans<<<(3 * 256 * D_IN + 255) / 256, 256>>>(cw0, 3, 0);
    k_wtrans<<<(5 * 256 * D_IN + 255) / 256, 256>>>(cw1, 5, 3 * 256 * D_IN);
    k_wtrans<<<(7 * 256 * D_IN + 255) / 256, 256>>>(cw2, 7, 8 * 256 * D_IN);

    // bf16 split conversions
    k_cvt<<<(int)(((long long)N * KPADX + 255) / 256), 256>>>(0, N);
    k_cvt<<<(int)(((long long)3840 * KPADX + 255) / 256), 256>>>(1, 3840);
    k_cvtw<<<(G4 * FDIM + 255) / 256, 256>>>(Wih,  0);
    k_cvtw<<<(G4 * FDIM + 255) / 256, 256>>>(Whh,  1);
    k_cvtw<<<(G4 * FDIM + 255) / 256, 256>>>(WihR, 2);
    k_cvtw<<<(G4 * FDIM + 255) / 256, 256>>>(WhhR, 3);

    int mt = (N + 127) / 128;
    dim3 cg(mt, 2);
    k_mmconv<<<cg, 256, SMEM_MMA>>>(3, 0, 0,   cb0, N);
    k_mmconv<<<cg, 256, SMEM_MMA>>>(5, 3, 256, cb1, N);
    k_mmconv<<<cg, 256, SMEM_MMA>>>(7, 8, 512, cb2, N);

    {
        long long tot = (long long)N * FDIM;
        k_pool<<<(int)((tot + 255) / 256), 256>>>(N);
        k_cvt<<<(int)((tot + 255) / 256), 256>>>(2, N);   // FEAT -> FB
        k_cvt<<<(int)((tot + 255) / 256), 256>>>(3, N);   // POOL -> PB
    }

    dim3 gg(mt, G4 / 128);
    // gx = pool @ Wih^T + b_ih + b_hh
    k_mmgate<<<gg, 256, SMEM_MMA>>>(0, 0, 0, 0, 0, bih, bhh, N);
    k_reset<<<48, 256>>>();
    k_scan<<<128, 384>>>(Whh, N, nChunks);
    {
        long long tot = (long long)N * FDIM;
        k_cvt<<<(int)((tot + 255) / 256), 256>>>(4, N);   // HS -> HB
    }

    // forward final cell: G = feat@Wih^T + h(-9)@Whh^T + b ; gates -> out[:, :768]
    k_mmgate<<<gg, 256, SMEM_MMA>>>(1, 0, 1, 1, -9, bih, bhh, N);
    {
        long long tot = (long long)N * FDIM;
        k_final<<<(int)((tot + 255) / 256), 256>>>(out, N, -9, 0);
    }
    // reverse final cell: out[:, 768:]
    k_mmgate<<<gg, 256, SMEM_MMA>>>(1, 2, 1, 3, 9, bihR, bhhR, N);
    {
        long long tot = (long long)N * FDIM;
        k_final<<<(int)((tot + 255) / 256), 256>>>(out, N, 9, 768);
    }
}

// round 5
// speedup vs baseline: 2.2474x; 1.0493x over previous
#include <cuda_runtime.h>
#include <cuda_bf16.h>
#include <math.h>
#include <stdint.h>

#define MAXN   25600
#define D_IN   1068
#define KPADX  1088
#define FDIM   768
#define G4     3072
#define NPE    200
#define MAXDOC 256

typedef unsigned long long ull;

// ---------------- scratch (static device arrays; no allocations) ----------------
__device__ float SC_PE  [NPE * D_IN];
__device__ int   SC_POS [MAXN];
__device__ float SC_XDOC[(size_t)MAXN * D_IN];
__device__ float SC_WT  [15 * 256 * D_IN];            // taps: 0..2 (k3), 3..7 (k5), 8..14 (k7)
__device__ float SC_FEAT[(size_t)MAXN * FDIM];
__device__ float SC_G   [(size_t)MAXN * G4];
__device__ float SC_CS  [(size_t)MAXN * FDIM];
__device__ float SC_H16 [2][16 * FDIM];
__device__ unsigned SC_ARRIVE;
__device__ unsigned SC_RELEASE;

// bf16 split planes (hi + lo), 16B aligned for cp.async
__device__ __align__(16) __nv_bfloat16 XBh[(size_t)MAXN * KPADX], XBl[(size_t)MAXN * KPADX];
__device__ __align__(16) __nv_bfloat16 WTBh[(size_t)3840 * KPADX], WTBl[(size_t)3840 * KPADX];
__device__ __align__(16) __nv_bfloat16 FBh[(size_t)MAXN * FDIM], FBl[(size_t)MAXN * FDIM];
__device__ __align__(16) __nv_bfloat16 PBh[(size_t)MAXN * FDIM], PBl[(size_t)MAXN * FDIM];
__device__ __align__(16) __nv_bfloat16 HBh[(size_t)MAXN * FDIM], HBl[(size_t)MAXN * FDIM];
__device__ __align__(16) __nv_bfloat16 WGBh[(size_t)4 * G4 * FDIM], WGBl[(size_t)4 * G4 * FDIM];

__device__ __forceinline__ float sigm(float x) { return 1.0f / (1.0f + expf(-x)); }

// ---- packed f32x2 helpers (scan) ----
__device__ __forceinline__ void ffma2(ull& d, ull a, ull b) {
    asm("fma.rn.f32x2 %0, %1, %2, %0;" : "+l"(d) : "l"(a), "l"(b));
}
__device__ __forceinline__ float2 up2(ull v) {
    float2 r; asm("mov.b64 {%0, %1}, %2;" : "=f"(r.x), "=f"(r.y) : "l"(v)); return r;
}

// ---- mma.sync / ldmatrix / cp.async (base PTX, compute_103-safe) ----
__device__ __forceinline__ uint32_t smem_u32(const void* p) {
    uint32_t a;
    asm("{ .reg .u64 t; cvta.to.shared.u64 t, %1; cvt.u32.u64 %0, t; }" : "=r"(a) : "l"(p));
    return a;
}
__device__ __forceinline__ void ldsm4(uint32_t* r, uint32_t addr) {
    asm volatile("ldmatrix.sync.aligned.m8n8.x4.shared.b16 {%0,%1,%2,%3}, [%4];"
        : "=r"(r[0]), "=r"(r[1]), "=r"(r[2]), "=r"(r[3]) : "r"(addr));
}
__device__ __forceinline__ void mma16816(float* c, const uint32_t* a, uint32_t b0, uint32_t b1) {
    asm volatile("mma.sync.aligned.m16n8k16.row.col.f32.bf16.bf16.f32 "
        "{%0,%1,%2,%3}, {%4,%5,%6,%7}, {%8,%9}, {%0,%1,%2,%3};"
        : "+f"(c[0]), "+f"(c[1]), "+f"(c[2]), "+f"(c[3])
        : "r"(a[0]), "r"(a[1]), "r"(a[2]), "r"(a[3]), "r"(b0), "r"(b1));
}
__device__ __forceinline__ void cpa16(uint32_t dst, const void* src, int valid) {
    asm volatile("cp.async.cg.shared.global [%0], [%1], 16, %2;"
        :: "r"(dst), "l"(src), "r"(valid ? 16 : 0) : "memory");
}
#define CP_COMMIT() asm volatile("cp.async.commit_group;" ::: "memory")
#define CP_WAIT1()  asm volatile("cp.async.wait_group 1;" ::: "memory")
#define CP_WAIT0()  asm volatile("cp.async.wait_group 0;" ::: "memory")

// ---- SMEM: 4 planes (Ah, Al, Bh, Bl) of 128 rows x 32 bf16, row stride 80B; 2 buffers ----
#define RS     80
#define PLANE  10240
#define BUFB   40960
#define SMEM_MMA (2 * BUFB)

// load one 128x32 plane (2 chunks of 16B per thread)
__device__ __forceinline__ void ldp(uint32_t sdst, const __nv_bfloat16* src, int ldk,
                                    int rowBase, int rowLim, int kcol, int tid) {
#pragma unroll
    for (int it = 0; it < 2; ++it) {
        int ch = tid + it * 256;
        int row = ch >> 2, c = ch & 3;
        int r = rowBase + row;
        int v = (r >= 0 && r < rowLim);
        const void* s = src + ((size_t)(v ? r : 0) * ldk + kcol + c * 8);
        cpa16(sdst + row * RS + c * 16, s, v);
    }
}

// per-warp compute on one 32-K block: 3 split combos, acc[2][8][4]
// B fragments loaded per-group to keep live registers ~100 (enables 2 CTAs/SM)
__device__ __forceinline__ void wcompute(uint32_t sbuf, int lane, int wm, int wn,
                                         float acc[2][8][4]) {
    int arow = wm * 32 + (lane & 15);
    int brow = wn * 64 + (lane & 7) + ((lane >> 4) << 3);
#pragma unroll
    for (int kh = 0; kh < 2; ++kh) {
        int acol = kh * 16 + ((lane >> 4) << 3);
        int bcol = kh * 16 + (((lane >> 3) & 1) << 3);
        uint32_t ah[2][4], al[2][4];
#pragma unroll
        for (int mt = 0; mt < 2; ++mt) {
            uint32_t ad = sbuf + (arow + mt * 16) * RS + acol * 2;
            ldsm4(ah[mt], ad);
            ldsm4(al[mt], ad + PLANE);
        }
#pragma unroll
        for (int g = 0; g < 4; ++g) {
            uint32_t bh[4], bl[4];
            uint32_t bd = sbuf + 2 * PLANE + (brow + g * 16) * RS + bcol * 2;
            ldsm4(bh, bd);
            ldsm4(bl, bd + PLANE);
#pragma unroll
            for (int mt = 0; mt < 2; ++mt)
#pragma unroll
                for (int sub = 0; sub < 2; ++sub) {
                    int nt = g * 2 + sub;
                    mma16816(acc[mt][nt], ah[mt], bh[sub * 2], bh[sub * 2 + 1]);
                    mma16816(acc[mt][nt], ah[mt], bl[sub * 2], bl[sub * 2 + 1]);
                    mma16816(acc[mt][nt], al[mt], bh[sub * 2], bh[sub * 2 + 1]);
                }
        }
    }
}

// ---------------- fused prep: PE table (all blocks) + posidx (block 0) ----------------
__global__ void k_prep(const int* __restrict__ dl, int ndocs, int N) {
    int idx = blockIdx.x * blockDim.x + threadIdx.x;
    if (idx < NPE * D_IN) {
        int pos = idx / D_IN, ch = idx % D_IN;
        int i = ch >> 1;
        float e = (2.0f * (float)i) / (float)D_IN;
        float ang = (float)pos / powf(10000.0f, e);
        SC_PE[idx] = (ch & 1) ? cosf(ang) : sinf(ang);
    }
    if (blockIdx.x == 0) {
        __shared__ int off[MAXDOC + 1];
        if (threadIdx.x == 0) {
            int s = 0;
            for (int d = 0; d < ndocs; ++d) { off[d] = s; s += dl[d]; }
            off[ndocs] = s;
        }
        __syncthreads();
        for (int n = threadIdx.x; n < N; n += blockDim.x) {
            int lo = 0, hi = ndocs;
            while (hi - lo > 1) { int mid = (lo + hi) >> 1; if (off[mid] <= n) lo = mid; else hi = mid; }
            SC_POS[n] = n - off[lo];
        }
    }
}

__global__ void k_addpe(const float* __restrict__ x, int N) {
    long long idx = (long long)blockIdx.x * blockDim.x + threadIdx.x;
    long long tot = (long long)N * D_IN;
    if (idx >= tot) return;
    int n  = (int)(idx / D_IN);
    int ch = (int)(idx % D_IN);
    SC_XDOC[idx] = x[idx] + SC_PE[SC_POS[n] * D_IN + ch];
}

// all three conv weights -> [tap][oc][c] layout in one launch
__global__ void k_wtrans_all(const float* __restrict__ w0, const float* __restrict__ w1,
                             const float* __restrict__ w2) {
    int idx = blockIdx.x * blockDim.x + threadIdx.x;
    const int per = 256 * D_IN;
    if (idx >= 15 * per) return;
    int t  = idx / per;
    int r  = idx - t * per;
    int oc = r / D_IN;
    int c  = r - oc * D_IN;
    const float* w; int ksz, tl;
    if (t < 3)      { w = w0; ksz = 3; tl = t; }
    else if (t < 8) { w = w1; ksz = 5; tl = t - 3; }
    else            { w = w2; ksz = 7; tl = t - 8; }
    SC_WT[idx] = w[((size_t)oc * D_IN + c) * ksz + tl];
}

// fp32 -> bf16 (hi, lo) split; sel 0 = XDOC, 1 = WT
__global__ void k_cvt(int sel, int rows) {
    const float* src; __nv_bfloat16 *hi, *lo;
    if (sel == 0) { src = SC_XDOC; hi = XBh; lo = XBl; }
    else          { src = SC_WT;   hi = WTBh; lo = WTBl; }
    long long idx = (long long)blockIdx.x * blockDim.x + threadIdx.x;
    long long tot = (long long)rows * KPADX;
    if (idx >= tot) return;
    int r = (int)(idx / KPADX), k = (int)(idx % KPADX);
    float v = (k < D_IN) ? src[(size_t)r * D_IN + k] : 0.f;
    __nv_bfloat16 h = __float2bfloat16(v);
    hi[idx] = h;
    lo[idx] = __float2bfloat16(v - __bfloat162float(h));
}

// all four gate weight splits in one launch
__global__ void k_cvtw_all(const float* __restrict__ s0, const float* __restrict__ s1,
                           const float* __restrict__ s2, const float* __restrict__ s3) {
    long long idx = (long long)blockIdx.x * blockDim.x + threadIdx.x;
    const long long per = (long long)G4 * FDIM;
    if (idx >= 4 * per) return;
    int slot = (int)(idx / per);
    long long r = idx - (long long)slot * per;
    const float* s = (slot == 0) ? s0 : (slot == 1) ? s1 : (slot == 2) ? s2 : s3;
    float v = s[r];
    __nv_bfloat16 h = __float2bfloat16(v);
    WGBh[idx] = h;
    WGBl[idx] = __float2bfloat16(v - __bfloat162float(h));
}

// ---------------- mma conv: SC_FEAT[:, ocBase+n0 .. +128] ----------------
__global__ __launch_bounds__(256, 2)
void k_mmconv(int ksz, int tapBase, int ocBase, const float* __restrict__ bias, int N) {
    extern __shared__ char smem[];
    uint32_t sb = smem_u32(smem);
    int tid = threadIdx.x, lane = tid & 31, wid = tid >> 5;
    int wm = wid & 3, wn = wid >> 2;
    int m0 = blockIdx.x * 128, n0 = blockIdx.y * 128;
    int pad = ksz >> 1;
    int nblk = ksz * 34;
    float acc[2][8][4] = {};

    auto load_blk = [&](int i) {
        int buf = i & 1;
        int p = i / 34, kb = i - p * 34;
        int sh = p - pad;
        uint32_t bb = sb + buf * BUFB;
        const __nv_bfloat16* wth = WTBh + (size_t)(tapBase + p) * 256 * KPADX;
        const __nv_bfloat16* wtl = WTBl + (size_t)(tapBase + p) * 256 * KPADX;
        ldp(bb,             XBh, KPADX, m0 + sh, N,   kb * 32, tid);
        ldp(bb + PLANE,     XBl, KPADX, m0 + sh, N,   kb * 32, tid);
        ldp(bb + 2 * PLANE, wth, KPADX, n0,      256, kb * 32, tid);
        ldp(bb + 3 * PLANE, wtl, KPADX, n0,      256, kb * 32, tid);
        CP_COMMIT();
    };

    load_blk(0);
    for (int i = 0; i < nblk; ++i) {
        if (i + 1 < nblk) { load_blk(i + 1); CP_WAIT1(); } else { CP_WAIT0(); }
        __syncthreads();
        wcompute(sb + (i & 1) * BUFB, lane, wm, wn, acc);
        __syncthreads();
    }

#pragma unroll
    for (int mt = 0; mt < 2; ++mt)
#pragma unroll
        for (int nt = 0; nt < 8; ++nt) {
            int col = n0 + wn * 64 + nt * 8 + (lane & 3) * 2;
            float b0 = bias[col], b1 = bias[col + 1];
            int r0 = m0 + wm * 32 + mt * 16 + (lane >> 2);
#pragma unroll
            for (int hh = 0; hh < 2; ++hh) {
                int m = r0 + hh * 8;
                if (m < N) {
                    float v0 = acc[mt][nt][hh * 2]     + b0;
                    float v1 = acc[mt][nt][hh * 2 + 1] + b1;
                    v0 = (v0 >= 0.f) ? v0 : 0.01f * v0;
                    v1 = (v1 >= 0.f) ? v1 : 0.01f * v1;
                    SC_FEAT[(size_t)m * FDIM + ocBase + col]     = v0;
                    SC_FEAT[(size_t)m * FDIM + ocBase + col + 1] = v1;
                }
            }
        }
}

// ---------------- mma gate GEMM: SC_G = A@W^T [+ A2(shift)@W2^T] + b1 + b2 ----------------
__global__ __launch_bounds__(256, 2)
void k_mmgate(int aSel, int wSlot, int pass2, int wSlot2, int shift2,
              const float* __restrict__ b1, const float* __restrict__ b2, int N) {
    extern __shared__ char smem[];
    uint32_t sb = smem_u32(smem);
    int tid = threadIdx.x, lane = tid & 31, wid = tid >> 5;
    int wm = wid & 3, wn = wid >> 2;
    int m0 = blockIdx.x * 128, n0 = blockIdx.y * 128;
    int nblk = pass2 ? 48 : 24;
    float acc[2][8][4] = {};

    auto load_blk = [&](int i) {
        int buf = i & 1;
        int p = i / 24, kb = i - p * 24;
        const __nv_bfloat16 *ah, *al, *bh, *bl;
        int sh;
        if (p == 0) {
            ah = aSel ? FBh : PBh; al = aSel ? FBl : PBl;
            bh = WGBh + (size_t)wSlot * G4 * FDIM;
            bl = WGBl + (size_t)wSlot * G4 * FDIM;
            sh = 0;
        } else {
            ah = HBh; al = HBl;
            bh = WGBh + (size_t)wSlot2 * G4 * FDIM;
            bl = WGBl + (size_t)wSlot2 * G4 * FDIM;
            sh = shift2;
        }
        uint32_t bb = sb + buf * BUFB;
        ldp(bb,             ah, FDIM, m0 + sh, N,  kb * 32, tid);
        ldp(bb + PLANE,     al, FDIM, m0 + sh, N,  kb * 32, tid);
        ldp(bb + 2 * PLANE, bh, FDIM, n0,      G4, kb * 32, tid);
        ldp(bb + 3 * PLANE, bl, FDIM, n0,      G4, kb * 32, tid);
        CP_COMMIT();
    };

    load_blk(0);
    for (int i = 0; i < nblk; ++i) {
        if (i + 1 < nblk) { load_blk(i + 1); CP_WAIT1(); } else { CP_WAIT0(); }
        __syncthreads();
        wcompute(sb + (i & 1) * BUFB, lane, wm, wn, acc);
        __syncthreads();
    }

#pragma unroll
    for (int mt = 0; mt < 2; ++mt)
#pragma unroll
        for (int nt = 0; nt < 8; ++nt) {
            int g = n0 + wn * 64 + nt * 8 + (lane & 3) * 2;
            float bv0 = b1[g] + b2[g];
            float bv1 = b1[g + 1] + b2[g + 1];
            int r0 = m0 + wm * 32 + mt * 16 + (lane >> 2);
#pragma unroll
            for (int hh = 0; hh < 2; ++hh) {
                int m = r0 + hh * 8;
                if (m < N) {
                    SC_G[(size_t)m * G4 + g]     = acc[mt][nt][hh * 2]     + bv0;
                    SC_G[(size_t)m * G4 + g + 1] = acc[mt][nt][hh * 2 + 1] + bv1;
                }
            }
        }
}

// ---------------- fused: FEAT -> FB planes; maxpool -> PB planes ----------------
__global__ void k_postconv(int N) {
    long long idx = (long long)blockIdx.x * blockDim.x + threadIdx.x;
    long long tot = (long long)N * FDIM;
    if (idx >= tot) return;
    int n = (int)(idx / FDIM), ch = (int)(idx % FDIM);
    float f = SC_FEAT[idx];
    __nv_bfloat16 fh = __float2bfloat16(f);
    FBh[idx] = fh;
    FBl[idx] = __float2bfloat16(f - __bfloat162float(fh));
    int ksz = 3 + 2 * (ch >> 8);
    int p = ksz >> 1;
    float m = f;
    for (int d = -p; d <= p; ++d) {
        int nn = n + d;
        if (d != 0 && nn >= 0 && nn < N) m = fmaxf(m, SC_FEAT[(long long)nn * FDIM + ch]);
    }
    __nv_bfloat16 mh = __float2bfloat16(m);
    PBh[idx] = mh;
    PBl[idx] = __float2bfloat16(m - __bfloat162float(mh));
}

__global__ void k_reset() {
    int idx = blockIdx.x * blockDim.x + threadIdx.x;
    if (idx == 0) { SC_ARRIVE = 0u; SC_RELEASE = 0u; }
    if (idx < 16 * FDIM) SC_H16[0][idx] = 0.f;
}

// ---------------- persistent chunked-LSTM scan (emits bf16 h planes directly) ----------------
__global__ void k_scan(const float* __restrict__ Whh, int N, int nChunks) {
    __shared__ float4 sh4[16 * 192];
    float* shp = (float*)sh4;
    int t = threadIdx.x, b = blockIdx.x;
    int j = t & 15;
    int q = t >> 4;
    int hl = q % 6, gate = q / 6;
    int h_idx = b * 6 + hl;
    int grow = gate * FDIM + h_idx;
    const float4* w4 = (const float4*)(Whh + (long long)grow * FDIM);
    float c_reg = 0.f;

    for (int s = 0; s < nChunks; ++s) {
        const float4* src = (const float4*)(SC_H16[s & 1]);
        for (int f = t; f < 3072; f += 384) {
            float4 v = __ldcg(src + f);
            int jj = f / 192, k4 = f - jj * 192;
            sh4[jj * 192 + (k4 ^ jj)] = v;
        }
        __syncthreads();

        int pos = s * 16 + j;
        float pre = 0.f;
        if (pos < N) {
            const float4* h4 = sh4 + j * 192;
            ull acc0 = 0, acc1 = 0;
#pragma unroll 4
            for (int k4 = 0; k4 < 192; ++k4) {
                float4 w = __ldg(w4 + k4);
                float4 h = h4[k4 ^ j];
                ull wlo, whi, hlo, hhi;
                asm("mov.b64 %0, {%1, %2};" : "=l"(wlo) : "f"(w.x), "f"(w.y));
                asm("mov.b64 %0, {%1, %2};" : "=l"(whi) : "f"(w.z), "f"(w.w));
                asm("mov.b64 %0, {%1, %2};" : "=l"(hlo) : "f"(h.x), "f"(h.y));
                asm("mov.b64 %0, {%1, %2};" : "=l"(hhi) : "f"(h.z), "f"(h.w));
                ffma2(acc0, wlo, hlo);
                ffma2(acc1, whi, hhi);
            }
            float2 s0 = up2(acc0), s1 = up2(acc1);
            pre = __ldg(&SC_G[(long long)pos * G4 + grow]) + ((s0.x + s0.y) + (s1.x + s1.y));
        }
        __syncthreads();
        shp[j * 24 + q] = pre;
        __syncthreads();

        if (q < 6 && pos < N) {
            float gi = shp[j * 24 + hl];
            float gf = shp[j * 24 + 6  + hl];
            float gg = shp[j * 24 + 12 + hl];
            float go = shp[j * 24 + 18 + hl];
            float c2 = sigm(gf) * c_reg + sigm(gi) * tanhf(gg);
            float h2 = sigm(go) * tanhf(c2);
            c_reg = c2;
            long long o = (long long)pos * FDIM + h_idx;
            SC_CS[o] = c2;
            __nv_bfloat16 hh = __float2bfloat16(h2);
            HBh[o] = hh;
            HBl[o] = __float2bfloat16(h2 - __bfloat162float(hh));
            SC_H16[(s + 1) & 1][j * FDIM + h_idx] = h2;
        }

        __threadfence();
        __syncthreads();
        if (t == 0) {
            unsigned prev = atomicAdd(&SC_ARRIVE, 1u);
            unsigned target = (unsigned)(s + 1) * gridDim.x;
            if (prev + 1 == target) {
                atomicExch(&SC_RELEASE, (unsigned)(s + 1));
            } else {
                while (*(volatile unsigned*)&SC_RELEASE < (unsigned)(s + 1)) __nanosleep(32);
            }
            __threadfence();
        }
        __syncthreads();
    }
}

// ---------------- final LSTM-cell gate fuse ----------------
__global__ void k_final(float* __restrict__ out, int N, int shift, int outOff) {
    long long idx = (long long)blockIdx.x * blockDim.x + threadIdx.x;
    long long tot = (long long)N * FDIM;
    if (idx >= tot) return;
    int n = (int)(idx / FDIM), h = (int)(idx % FDIM);
    int ns = n + shift;
    float cin = (ns >= 0 && ns < N) ? SC_CS[(long long)ns * FDIM + h] : 0.f;
    const float* g = SC_G + (long long)n * G4;
    float gi = g[h], gf = g[FDIM + h], gg = g[2 * FDIM + h], go = g[3 * FDIM + h];
    float c2 = sigm(gf) * cin + sigm(gi) * tanhf(gg);
    out[(long long)n * 1536 + outOff + h] = sigm(go) * tanhf(c2);
}

// ---------------- launch ----------------
extern "C" void kernel_launch(void* const* d_in, const int* in_sizes, int n_in,
                              void* d_out, int out_size) {
    const float* x    = (const float*)d_in[0];
    const int*   dl   = (const int*)  d_in[1];
    const float* cw0  = (const float*)d_in[2];  const float* cb0 = (const float*)d_in[3];
    const float* cw1  = (const float*)d_in[4];  const float* cb1 = (const float*)d_in[5];
    const float* cw2  = (const float*)d_in[6];  const float* cb2 = (const float*)d_in[7];
    const float* Wih  = (const float*)d_in[8];  const float* Whh  = (const float*)d_in[9];
    const float* bih  = (const float*)d_in[10]; const float* bhh  = (const float*)d_in[11];
    const float* WihR = (const float*)d_in[12]; const float* WhhR = (const float*)d_in[13];
    const float* bihR = (const float*)d_in[14]; const float* bhhR = (const float*)d_in[15];
    float* out = (float*)d_out;

    int ndocs = in_sizes[1];
    int N = out_size / 1536;
    if (N > MAXN) N = MAXN;
    int nChunks = (N + 15) / 16;

    cudaFuncSetAttribute(k_mmconv, cudaFuncAttributeMaxDynamicSharedMemorySize, SMEM_MMA);
    cudaFuncSetAttribute(k_mmgate, cudaFuncAttributeMaxDynamicSharedMemorySize, SMEM_MMA);

    // launch 0
    k_prep<<<(NPE * D_IN + 255) / 256, 256>>>(dl, ndocs, N);
    // launch 1
    {
        long long tot = (long long)N * D_IN;
        k_addpe<<<(int)((tot + 255) / 256), 256>>>(x, N);
    }
    // launch 2
    k_wtrans_all<<<(15 * 256 * D_IN + 255) / 256, 256>>>(cw0, cw1, cw2);
    // launch 3, 4
    k_cvt<<<(int)(((long long)N * KPADX + 255) / 256), 256>>>(0, N);
    k_cvt<<<(int)(((long long)3840 * KPADX + 255) / 256), 256>>>(1, 3840);

    int mt = (N + 127) / 128;
    dim3 cg(mt, 2);
    // launch 5: the big k=7 conv — ncu capture target
    k_mmconv<<<cg, 256, SMEM_MMA>>>(7, 8, 512, cb2, N);
    k_mmconv<<<cg, 256, SMEM_MMA>>>(5, 3, 256, cb1, N);
    k_mmconv<<<cg, 256, SMEM_MMA>>>(3, 0, 0,   cb0, N);

    {
        long long tot = (long long)N * FDIM;
        k_postconv<<<(int)((tot + 255) / 256), 256>>>(N);
    }
    k_cvtw_all<<<(int)((4LL * G4 * FDIM + 255) / 256), 256>>>(Wih, Whh, WihR, WhhR);

    dim3 gg(mt, G4 / 128);
    // gx = pool @ Wih^T + b_ih + b_hh
    k_mmgate<<<gg, 256, SMEM_MMA>>>(0, 0, 0, 0, 0, bih, bhh, N);
    k_reset<<<48, 256>>>();
    k_scan<<<128, 384>>>(Whh, N, nChunks);

    // forward final cell: G = feat@Wih^T + h(-9)@Whh^T + b ; gates -> out[:, :768]
    k_mmgate<<<gg, 256, SMEM_MMA>>>(1, 0, 1, 1, -9, bih, bhh, N);
    {
        long long tot = (long long)N * FDIM;
        k_final<<<(int)((tot + 255) / 256), 256>>>(out, N, -9, 0);
    }
    // reverse final cell: out[:, 768:]
    k_mmgate<<<gg, 256, SMEM_MMA>>>(1, 2, 1, 3, 9, bihR, bhhR, N);
    {
        long long tot = (long long)N * FDIM;
        k_final<<<(int)((tot + 255) / 256), 256>>>(out, N, 9, 768);
    }
}